// round 1
// baseline (speedup 1.0000x reference)
#include <cuda_runtime.h>

// WeightedMseLoss: out = mean( (x - y)^2 * weight_table[round(y*100)] )
// Inputs (metadata order): d_in[0]=x (f32, N), d_in[1]=y (f32, N), d_in[2]=weight_table (f32, 101)
// Output: 1 x f32 scalar.
//
// HBM-bound streaming reduction. Two-pass deterministic reduce:
//   pass 1: grid-stride float4 loads, smem weight table, block partial -> g_partials
//   pass 2: single block sums g_partials, scales by 1/N, writes d_out[0].

#define NBLOCKS   2048
#define NTHREADS  256
#define NUM_LEVELS 101

__device__ float g_partials[NBLOCKS];

__global__ __launch_bounds__(NTHREADS) void wmse_partial_kernel(
    const float* __restrict__ x,
    const float* __restrict__ y,
    const float* __restrict__ wt,
    int n4)  // number of float4 vectors
{
    __shared__ float s_w[NUM_LEVELS];
    const int t = threadIdx.x;
    if (t < NUM_LEVELS) s_w[t] = wt[t];
    __syncthreads();

    const float4* __restrict__ x4 = reinterpret_cast<const float4*>(x);
    const float4* __restrict__ y4 = reinterpret_cast<const float4*>(y);

    float acc = 0.0f;
    const int stride = gridDim.x * blockDim.x;
    int i = blockIdx.x * blockDim.x + t;

    // 2-deep unroll for memory-level parallelism (4 independent 16B LDGs in flight)
    for (; i + stride < n4; i += 2 * stride) {
        float4 xa = x4[i];
        float4 ya = y4[i];
        float4 xb = x4[i + stride];
        float4 yb = y4[i + stride];

        int ia0 = __float2int_rn(ya.x * 100.0f);
        int ia1 = __float2int_rn(ya.y * 100.0f);
        int ia2 = __float2int_rn(ya.z * 100.0f);
        int ia3 = __float2int_rn(ya.w * 100.0f);
        float da0 = xa.x - ya.x, da1 = xa.y - ya.y;
        float da2 = xa.z - ya.z, da3 = xa.w - ya.w;
        acc = fmaf(da0 * da0, s_w[ia0], acc);
        acc = fmaf(da1 * da1, s_w[ia1], acc);
        acc = fmaf(da2 * da2, s_w[ia2], acc);
        acc = fmaf(da3 * da3, s_w[ia3], acc);

        int ib0 = __float2int_rn(yb.x * 100.0f);
        int ib1 = __float2int_rn(yb.y * 100.0f);
        int ib2 = __float2int_rn(yb.z * 100.0f);
        int ib3 = __float2int_rn(yb.w * 100.0f);
        float db0 = xb.x - yb.x, db1 = xb.y - yb.y;
        float db2 = xb.z - yb.z, db3 = xb.w - yb.w;
        acc = fmaf(db0 * db0, s_w[ib0], acc);
        acc = fmaf(db1 * db1, s_w[ib1], acc);
        acc = fmaf(db2 * db2, s_w[ib2], acc);
        acc = fmaf(db3 * db3, s_w[ib3], acc);
    }
    // tail (at most one extra grid-stride step)
    for (; i < n4; i += stride) {
        float4 xv = x4[i];
        float4 yv = y4[i];
        int i0 = __float2int_rn(yv.x * 100.0f);
        int i1 = __float2int_rn(yv.y * 100.0f);
        int i2 = __float2int_rn(yv.z * 100.0f);
        int i3 = __float2int_rn(yv.w * 100.0f);
        float d0 = xv.x - yv.x, d1 = xv.y - yv.y;
        float d2 = xv.z - yv.z, d3 = xv.w - yv.w;
        acc = fmaf(d0 * d0, s_w[i0], acc);
        acc = fmaf(d1 * d1, s_w[i1], acc);
        acc = fmaf(d2 * d2, s_w[i2], acc);
        acc = fmaf(d3 * d3, s_w[i3], acc);
    }

    // warp reduce
    #pragma unroll
    for (int o = 16; o > 0; o >>= 1)
        acc += __shfl_down_sync(0xffffffffu, acc, o);

    __shared__ float s_sum[NTHREADS / 32];
    if ((t & 31) == 0) s_sum[t >> 5] = acc;
    __syncthreads();

    if (t < 32) {
        float v = (t < NTHREADS / 32) ? s_sum[t] : 0.0f;
        #pragma unroll
        for (int o = 4; o > 0; o >>= 1)
            v += __shfl_down_sync(0xffffffffu, v, o);
        if (t == 0) g_partials[blockIdx.x] = v;
    }
}

__global__ __launch_bounds__(1024) void wmse_final_kernel(float* __restrict__ out, float invN)
{
    const int t = threadIdx.x;
    float acc = 0.0f;
    for (int i = t; i < NBLOCKS; i += 1024)
        acc += g_partials[i];

    #pragma unroll
    for (int o = 16; o > 0; o >>= 1)
        acc += __shfl_down_sync(0xffffffffu, acc, o);

    __shared__ float s_sum[32];
    if ((t & 31) == 0) s_sum[t >> 5] = acc;
    __syncthreads();

    if (t < 32) {
        float v = s_sum[t];
        #pragma unroll
        for (int o = 16; o > 0; o >>= 1)
            v += __shfl_down_sync(0xffffffffu, v, o);
        if (t == 0) out[0] = v * invN;
    }
}

extern "C" void kernel_launch(void* const* d_in, const int* in_sizes, int n_in,
                              void* d_out, int out_size)
{
    const float* x  = (const float*)d_in[0];
    const float* y  = (const float*)d_in[1];
    const float* wt = (const float*)d_in[2];
    float* out = (float*)d_out;

    const int n  = in_sizes[0];
    const int n4 = n >> 2;  // N = 2^24, divisible by 4

    wmse_partial_kernel<<<NBLOCKS, NTHREADS>>>(x, y, wt, n4);
    wmse_final_kernel<<<1, 1024>>>(out, 1.0f / (float)n);
}